// round 2
// baseline (speedup 1.0000x reference)
#include <cuda_runtime.h>
#include <cuda_bf16.h>
#include <cstdint>

#define N_NODES 50000
#define N_EDGES 1600000
#define DIM     128
#define N_LAYERS 4
#define N_GRAPHS 512
#define M_TILES  391            // ceil(50000/128)
#define M_PAD    (M_TILES*128)  // 50048

// ---------------- scratch (static device globals; no allocation) -------------
__device__ int   g_deg[N_NODES];
__device__ int   g_rowstart[N_NODES + 1];
__device__ int   g_cursor[N_NODES];
__device__ int   g_csr[N_EDGES];
__device__ float g_hin[M_PAD * DIM];   // x + agg   (padded rows stay 0)
__device__ float g_hmid[M_PAD * DIM];  // relu(hin@W1+b1)
__device__ float g_xbuf[M_PAD * DIM];  // hmid@W2+b2

// ---------------- packed fp32x2 FMA (Blackwell FFMA2) ------------------------
__device__ __forceinline__ unsigned long long ffma2(unsigned long long a,
                                                    unsigned long long b,
                                                    unsigned long long c) {
    unsigned long long d;
    asm("fma.rn.f32x2 %0, %1, %2, %3;" : "=l"(d) : "l"(a), "l"(b), "l"(c));
    return d;
}
__device__ __forceinline__ unsigned long long dup2(float f) {
    unsigned u = __float_as_uint(f);
    return ((unsigned long long)u << 32) | (unsigned long long)u;
}

// ---------------- CSR build --------------------------------------------------
__global__ void k_zero_deg() {
    int i = blockIdx.x * blockDim.x + threadIdx.x;
    if (i < N_NODES) g_deg[i] = 0;
}

__global__ void k_hist(const int* __restrict__ ei) {
    int e = blockIdx.x * blockDim.x + threadIdx.x;
    if (e < N_EDGES) atomicAdd(&g_deg[ei[N_EDGES + e]], 1);
}

// single-block exclusive scan over 50000 ints
__global__ void k_scan() {
    __shared__ int sh[1024];
    __shared__ int carry_sh;
    int tid = threadIdx.x;
    if (tid == 0) carry_sh = 0;
    __syncthreads();
    for (int base = 0; base < N_NODES; base += 1024) {
        int i = base + tid;
        int v = (i < N_NODES) ? g_deg[i] : 0;
        sh[tid] = v;
        __syncthreads();
        #pragma unroll
        for (int off = 1; off < 1024; off <<= 1) {
            int t = (tid >= off) ? sh[tid - off] : 0;
            __syncthreads();
            sh[tid] += t;
            __syncthreads();
        }
        int excl = sh[tid] - v + carry_sh;
        if (i < N_NODES) { g_rowstart[i] = excl; g_cursor[i] = excl; }
        __syncthreads();
        if (tid == 1023) carry_sh += sh[1023];
        __syncthreads();
    }
    if (tid == 0) g_rowstart[N_NODES] = carry_sh;
}

__global__ void k_scatter(const int* __restrict__ ei) {
    int e = blockIdx.x * blockDim.x + threadIdx.x;
    if (e < N_EDGES) {
        int src = ei[e];
        int dst = ei[N_EDGES + e];
        int p = atomicAdd(&g_cursor[dst], 1);
        g_csr[p] = src;
    }
}

// ---------------- aggregation: hout[n] = xin[n] + sum_{s in N(n)} xin[s] -----
__global__ void k_agg(const float* __restrict__ xin, float* __restrict__ hout) {
    int warp = (blockIdx.x * blockDim.x + threadIdx.x) >> 5;
    int lane = threadIdx.x & 31;
    if (warp >= N_NODES) return;
    const float4* x4 = (const float4*)xin;
    float4 acc = x4[(size_t)warp * 32 + lane];
    int s = g_rowstart[warp];
    int e = g_rowstart[warp + 1];
    #pragma unroll 4
    for (int j = s; j < e; j++) {
        int src = __ldg(&g_csr[j]);
        float4 v = __ldg(&x4[(size_t)src * 32 + lane]);
        acc.x += v.x; acc.y += v.y; acc.z += v.z; acc.w += v.w;
    }
    ((float4*)hout)[(size_t)warp * 32 + lane] = acc;
}

// ---------------- fp32x2 GEMM: C[M_PAD,128] = A[M_PAD,128] @ W[128,128] + b --
template <bool RELU>
__global__ __launch_bounds__(256, 2) void k_gemm(const float* __restrict__ A,
                                                 const float* __restrict__ W,
                                                 const float* __restrict__ bias,
                                                 float* __restrict__ C) {
    __shared__ __align__(16) float sA[16][132];              // [kk][row], padded
    __shared__ __align__(16) unsigned long long sB[16][128]; // [kk][col] dup pair
    const int tid = threadIdx.x;
    const int row0 = blockIdx.x * 128;
    const int tr = tid >> 4;        // 0..15
    const int tc = tid & 15;        // 0..15
    const int rbase = tr * 8;       // rows rbase..rbase+7
    const int cbase = tc * 8;       // cols cbase..cbase+7

    unsigned long long acc[4][8];
    #pragma unroll
    for (int i = 0; i < 4; i++)
        #pragma unroll
        for (int j = 0; j < 8; j++) acc[i][j] = 0ULL;

    for (int k0 = 0; k0 < 128; k0 += 16) {
        // A tile -> transposed smem: 512 float4, 2 per thread
        #pragma unroll
        for (int i = 0; i < 2; i++) {
            int idx = tid * 2 + i;          // 0..511
            int r = idx >> 2;               // 0..127
            int kc = (idx & 3) * 4;         // 0,4,8,12
            float4 v = *(const float4*)&A[(size_t)(row0 + r) * DIM + k0 + kc];
            sA[kc + 0][r] = v.x; sA[kc + 1][r] = v.y;
            sA[kc + 2][r] = v.z; sA[kc + 3][r] = v.w;
        }
        // W tile -> duplicated-pair smem
        #pragma unroll
        for (int i = 0; i < 2; i++) {
            int idx = tid * 2 + i;          // 0..511
            int kk = idx >> 5;              // 0..15
            int c = (idx & 31) * 4;         // 0..124
            float4 v = *(const float4*)&W[(size_t)(k0 + kk) * DIM + c];
            sB[kk][c + 0] = dup2(v.x); sB[kk][c + 1] = dup2(v.y);
            sB[kk][c + 2] = dup2(v.z); sB[kk][c + 3] = dup2(v.w);
        }
        __syncthreads();
        #pragma unroll
        for (int kk = 0; kk < 16; kk++) {
            unsigned long long a2[4];
            const unsigned long long* ap =
                (const unsigned long long*)&sA[kk][rbase];
            #pragma unroll
            for (int i = 0; i < 4; i++) a2[i] = ap[i];
            unsigned long long b2[8];
            const unsigned long long* bp = &sB[kk][cbase];
            #pragma unroll
            for (int j = 0; j < 8; j++) b2[j] = bp[j];
            #pragma unroll
            for (int i = 0; i < 4; i++)
                #pragma unroll
                for (int j = 0; j < 8; j++)
                    acc[i][j] = ffma2(a2[i], b2[j], acc[i][j]);
        }
        __syncthreads();
    }

    float bv[8];
    #pragma unroll
    for (int j = 0; j < 8; j++) bv[j] = bias[cbase + j];

    #pragma unroll
    for (int i = 0; i < 4; i++) {
        int r_lo = row0 + rbase + 2 * i;
        float o0[8], o1[8];
        #pragma unroll
        for (int j = 0; j < 8; j++) {
            unsigned long long v = acc[i][j];
            float lo = __uint_as_float((unsigned)v) + bv[j];
            float hi = __uint_as_float((unsigned)(v >> 32)) + bv[j];
            if (RELU) { lo = fmaxf(lo, 0.f); hi = fmaxf(hi, 0.f); }
            o0[j] = lo; o1[j] = hi;
        }
        *(float4*)&C[(size_t)r_lo * DIM + cbase] =
            make_float4(o0[0], o0[1], o0[2], o0[3]);
        *(float4*)&C[(size_t)r_lo * DIM + cbase + 4] =
            make_float4(o0[4], o0[5], o0[6], o0[7]);
        *(float4*)&C[(size_t)(r_lo + 1) * DIM + cbase] =
            make_float4(o1[0], o1[1], o1[2], o1[3]);
        *(float4*)&C[(size_t)(r_lo + 1) * DIM + cbase + 4] =
            make_float4(o1[4], o1[5], o1[6], o1[7]);
    }
}

// ---------------- pooling: batch is sorted -> one block per graph ------------
__global__ void k_pool(const float* __restrict__ x,
                       const int* __restrict__ batch,
                       float* __restrict__ out) {
    int g = blockIdx.x;
    int c = threadIdx.x;   // 0..127
    int a = 0, b = N_NODES;
    while (a < b) { int m = (a + b) >> 1; if (batch[m] < g) a = m + 1; else b = m; }
    int lo = a;
    b = N_NODES;
    while (a < b) { int m = (a + b) >> 1; if (batch[m] < g + 1) a = m + 1; else b = m; }
    int hi = a;
    float s = 0.f;
    for (int i = lo; i < hi; i++) s += x[(size_t)i * DIM + c];
    out[(size_t)g * DIM + c] = s;
}

// ---------------- launch -----------------------------------------------------
extern "C" void kernel_launch(void* const* d_in, const int* in_sizes, int n_in,
                              void* d_out, int out_size) {
    const float* x   = (const float*)d_in[0];
    const int* ei    = (const int*)d_in[1];   // int32! (JAX x64 disabled)
    const int* bat   = (const int*)d_in[2];   // int32!
    const float* Ws1 = (const float*)d_in[3];
    const float* bs1 = (const float*)d_in[4];
    const float* Ws2 = (const float*)d_in[5];
    const float* bs2 = (const float*)d_in[6];
    float* out       = (float*)d_out;

    void* p;
    cudaGetSymbolAddress(&p, g_hin);  float* hin  = (float*)p;
    cudaGetSymbolAddress(&p, g_hmid); float* hmid = (float*)p;
    cudaGetSymbolAddress(&p, g_xbuf); float* xb   = (float*)p;

    k_zero_deg<<<(N_NODES + 255) / 256, 256>>>();
    k_hist<<<(N_EDGES + 255) / 256, 256>>>(ei);
    k_scan<<<1, 1024>>>();
    k_scatter<<<(N_EDGES + 255) / 256, 256>>>(ei);

    const int agg_blocks = (N_NODES * 32 + 255) / 256;
    for (int l = 0; l < N_LAYERS; l++) {
        const float* xin = (l == 0) ? x : xb;
        k_agg<<<agg_blocks, 256>>>(xin, hin);
        k_gemm<true><<<M_TILES, 256>>>(hin, Ws1 + (size_t)l * DIM * DIM,
                                       bs1 + (size_t)l * DIM, hmid);
        k_gemm<false><<<M_TILES, 256>>>(hmid, Ws2 + (size_t)l * DIM * DIM,
                                        bs2 + (size_t)l * DIM, xb);
    }
    k_pool<<<N_GRAPHS, DIM>>>(xb, bat, out);
}

// round 3
// speedup vs baseline: 1.9642x; 1.9642x over previous
#include <cuda_runtime.h>
#include <cuda_bf16.h>
#include <cstdint>

#define N_NODES 50000
#define N_EDGES 1600000
#define DIM     128
#define N_LAYERS 4
#define N_GRAPHS 512
#define M_TILES  391            // ceil(50000/128)
#define M_PAD    (M_TILES*128)  // 50048
#define SCAN_BLOCKS 49          // 49*1024 >= 50000

typedef unsigned long long ull;

// ---------------- scratch (static device globals; no allocation) -------------
__device__ int   g_deg[N_NODES];
__device__ int   g_rowstart[N_NODES + 1];
__device__ int   g_cursor[N_NODES];
__device__ int   g_bsum[SCAN_BLOCKS];
__device__ int   g_boff[SCAN_BLOCKS];
__device__ int   g_csr[N_EDGES];
__device__ float g_hin[M_PAD * DIM];   // x + agg   (padded rows stay 0 forever)
__device__ float g_hmid[M_PAD * DIM];
__device__ float g_xbuf[M_PAD * DIM];

// ---------------- packed fp32x2 FMA (Blackwell FFMA2) ------------------------
__device__ __forceinline__ ull ffma2(ull a, ull b, ull c) {
    ull d;
    asm("fma.rn.f32x2 %0, %1, %2, %3;" : "=l"(d) : "l"(a), "l"(b), "l"(c));
    return d;
}
__device__ __forceinline__ ull dup2(float f) {
    ull d;
    asm("mov.b64 %0, {%1, %1};" : "=l"(d) : "f"(f));
    return d;
}

// ---------------- CSR build --------------------------------------------------
__global__ void k_zero_deg() {
    int i = blockIdx.x * blockDim.x + threadIdx.x;
    if (i < N_NODES) g_deg[i] = 0;
}

__global__ void k_hist(const int* __restrict__ ei) {
    int e = blockIdx.x * blockDim.x + threadIdx.x;
    if (e < N_EDGES) atomicAdd(&g_deg[ei[N_EDGES + e]], 1);
}

// hierarchical scan: part -> top -> add
__global__ void k_scan_part() {
    __shared__ int sh[1024];
    int t = threadIdx.x;
    int i = blockIdx.x * 1024 + t;
    int v = (i < N_NODES) ? g_deg[i] : 0;
    sh[t] = v;
    __syncthreads();
    #pragma unroll
    for (int off = 1; off < 1024; off <<= 1) {
        int u = (t >= off) ? sh[t - off] : 0;
        __syncthreads();
        sh[t] += u;
        __syncthreads();
    }
    if (i < N_NODES) g_rowstart[i] = sh[t] - v;   // local exclusive
    if (t == 1023) g_bsum[blockIdx.x] = sh[1023];
}

__global__ void k_scan_top() {
    __shared__ int sh[64];
    int t = threadIdx.x;
    int v = (t < SCAN_BLOCKS) ? g_bsum[t] : 0;
    sh[t] = v;
    __syncthreads();
    #pragma unroll
    for (int off = 1; off < 64; off <<= 1) {
        int u = (t >= off) ? sh[t - off] : 0;
        __syncthreads();
        sh[t] += u;
        __syncthreads();
    }
    if (t < SCAN_BLOCKS) g_boff[t] = sh[t] - v;   // exclusive
    if (t == SCAN_BLOCKS - 1) g_rowstart[N_NODES] = sh[t];
}

__global__ void k_scan_add() {
    int t = threadIdx.x;
    int i = blockIdx.x * 1024 + t;
    if (i < N_NODES) {
        int r = g_rowstart[i] + g_boff[blockIdx.x];
        g_rowstart[i] = r;
        g_cursor[i]   = r;
    }
}

__global__ void k_scatter(const int* __restrict__ ei) {
    int e = blockIdx.x * blockDim.x + threadIdx.x;
    if (e < N_EDGES) {
        int src = ei[e];
        int dst = ei[N_EDGES + e];
        int p = atomicAdd(&g_cursor[dst], 1);
        g_csr[p] = src;
    }
}

// ---------------- aggregation: hout[n] = xin[n] + sum_{s in N(n)} xin[s] -----
__global__ void k_agg(const float* __restrict__ xin, float* __restrict__ hout) {
    int warp = (blockIdx.x * blockDim.x + threadIdx.x) >> 5;
    int lane = threadIdx.x & 31;
    if (warp >= N_NODES) return;
    const float4* x4 = (const float4*)xin;
    float4 acc = x4[(size_t)warp * 32 + lane];
    int s = g_rowstart[warp];
    int e = g_rowstart[warp + 1];
    int j = s;
    // 8-deep software pipeline: batch indices, then 8 in-flight gathers
    for (; j + 8 <= e; j += 8) {
        int idx[8];
        #pragma unroll
        for (int t = 0; t < 8; t++) idx[t] = __ldg(&g_csr[j + t]);
        float4 v[8];
        #pragma unroll
        for (int t = 0; t < 8; t++) v[t] = __ldg(&x4[(size_t)idx[t] * 32 + lane]);
        #pragma unroll
        for (int t = 0; t < 8; t++) {
            acc.x += v[t].x; acc.y += v[t].y; acc.z += v[t].z; acc.w += v[t].w;
        }
    }
    for (; j < e; j++) {
        int src = __ldg(&g_csr[j]);
        float4 v = __ldg(&x4[(size_t)src * 32 + lane]);
        acc.x += v.x; acc.y += v.y; acc.z += v.z; acc.w += v.w;
    }
    ((float4*)hout)[(size_t)warp * 32 + lane] = acc;
}

// ---------------- fp32x2 GEMM: C[M_PAD,128] = A[M_PAD,128] @ W[128,128] + b --
// Accumulator pairs span COLUMN pairs (b = natural LDS.64 col-pair from padded
// plain-float W tile; a = broadcast dup-pair from transposed smem A tile).
#define W_STRIDE 160                     // 128 + 2 pads per 8 floats
#define A_STRIDE 132                     // ull stride per kk row
#define SW_FLOATS (128 * W_STRIDE)       // 20480 floats = 81920 B
#define SA_ULLS   (16 * A_STRIDE)        // 2112 ull    = 16896 B
#define GEMM_SMEM (SW_FLOATS * 4 + SA_ULLS * 8)   // 98816 B

__device__ __forceinline__ int widx(int c) { return c + ((c >> 3) << 1); }

template <bool RELU>
__global__ __launch_bounds__(256, 2) void k_gemm(const float* __restrict__ A,
                                                 const float* __restrict__ W,
                                                 const float* __restrict__ bias,
                                                 float* __restrict__ C) {
    extern __shared__ __align__(16) float smem[];
    float* sW  = smem;                          // [128][W_STRIDE] plain floats
    ull*   sA2 = (ull*)(smem + SW_FLOATS);      // [16][A_STRIDE] dup pairs

    const int tid  = threadIdx.x;
    const int row0 = blockIdx.x * 128;
    const int tr = tid >> 4;        // 0..15
    const int tc = tid & 15;        // 0..15
    const int rbase = tr * 8;       // rows rbase..rbase+7
    const int cbase = tc * 8;       // cols cbase..cbase+7 (4 col-pairs)

    // ---- load full W once: 16 float4 per thread ----
    #pragma unroll
    for (int it = 0; it < 16; it++) {
        int idx = tid + it * 256;            // 0..4095 float4s
        int k = idx >> 5;                    // 0..127
        int c = (idx & 31) * 4;              // 0..124
        float4 v = *(const float4*)&W[(size_t)k * DIM + c];
        float* dstp = &sW[k * W_STRIDE + widx(c)];   // c%8 in {0,4}: contiguous
        dstp[0] = v.x; dstp[1] = v.y; dstp[2] = v.z; dstp[3] = v.w;
    }

    ull acc[8][4];
    #pragma unroll
    for (int i = 0; i < 8; i++)
        #pragma unroll
        for (int j = 0; j < 4; j++) acc[i][j] = 0ULL;

    for (int k0 = 0; k0 < 128; k0 += 16) {
        __syncthreads();
        // A tile -> transposed dup-pair smem: 512 float4 loads, 2 per thread
        #pragma unroll
        for (int i = 0; i < 2; i++) {
            int idx = tid * 2 + i;          // 0..511
            int r = idx >> 2;               // 0..127
            int kc = (idx & 3) * 4;         // 0,4,8,12
            float4 v = *(const float4*)&A[(size_t)(row0 + r) * DIM + k0 + kc];
            sA2[(kc + 0) * A_STRIDE + r] = dup2(v.x);
            sA2[(kc + 1) * A_STRIDE + r] = dup2(v.y);
            sA2[(kc + 2) * A_STRIDE + r] = dup2(v.z);
            sA2[(kc + 3) * A_STRIDE + r] = dup2(v.w);
        }
        __syncthreads();
        #pragma unroll
        for (int kk = 0; kk < 16; kk++) {
            ull b2[4];
            const float* wrow = &sW[(k0 + kk) * W_STRIDE + 10 * tc];
            #pragma unroll
            for (int j = 0; j < 4; j++)
                b2[j] = *(const ull*)&wrow[2 * j];
            ull a2[8];
            const ull* arow = &sA2[kk * A_STRIDE + rbase];
            #pragma unroll
            for (int i = 0; i < 8; i++) a2[i] = arow[i];
            #pragma unroll
            for (int i = 0; i < 8; i++)
                #pragma unroll
                for (int j = 0; j < 4; j++)
                    acc[i][j] = ffma2(a2[i], b2[j], acc[i][j]);
        }
    }

    float bv[8];
    #pragma unroll
    for (int j = 0; j < 8; j++) bv[j] = bias[cbase + j];

    #pragma unroll
    for (int i = 0; i < 8; i++) {
        int r = row0 + rbase + i;
        float o[8];
        #pragma unroll
        for (int j = 0; j < 4; j++) {
            ull v = acc[i][j];
            float lo = __uint_as_float((unsigned)v)        + bv[2 * j];
            float hi = __uint_as_float((unsigned)(v >> 32)) + bv[2 * j + 1];
            if (RELU) { lo = fmaxf(lo, 0.f); hi = fmaxf(hi, 0.f); }
            o[2 * j] = lo; o[2 * j + 1] = hi;
        }
        *(float4*)&C[(size_t)r * DIM + cbase]     = make_float4(o[0], o[1], o[2], o[3]);
        *(float4*)&C[(size_t)r * DIM + cbase + 4] = make_float4(o[4], o[5], o[6], o[7]);
    }
}

// ---------------- pooling: batch is sorted -> one block per graph ------------
__global__ void k_pool(const float* __restrict__ x,
                       const int* __restrict__ batch,
                       float* __restrict__ out) {
    int g = blockIdx.x;
    int c = threadIdx.x;   // 0..127
    int a = 0, b = N_NODES;
    while (a < b) { int m = (a + b) >> 1; if (batch[m] < g) a = m + 1; else b = m; }
    int lo = a;
    b = N_NODES;
    while (a < b) { int m = (a + b) >> 1; if (batch[m] < g + 1) a = m + 1; else b = m; }
    int hi = a;
    float s0 = 0.f, s1 = 0.f, s2 = 0.f, s3 = 0.f;
    int i = lo;
    for (; i + 4 <= hi; i += 4) {
        s0 += x[(size_t)(i + 0) * DIM + c];
        s1 += x[(size_t)(i + 1) * DIM + c];
        s2 += x[(size_t)(i + 2) * DIM + c];
        s3 += x[(size_t)(i + 3) * DIM + c];
    }
    for (; i < hi; i++) s0 += x[(size_t)i * DIM + c];
    out[(size_t)g * DIM + c] = (s0 + s1) + (s2 + s3);
}

// ---------------- launch -----------------------------------------------------
extern "C" void kernel_launch(void* const* d_in, const int* in_sizes, int n_in,
                              void* d_out, int out_size) {
    const float* x   = (const float*)d_in[0];
    const int* ei    = (const int*)d_in[1];   // int32 (JAX x64 disabled)
    const int* bat   = (const int*)d_in[2];   // int32
    const float* Ws1 = (const float*)d_in[3];
    const float* bs1 = (const float*)d_in[4];
    const float* Ws2 = (const float*)d_in[5];
    const float* bs2 = (const float*)d_in[6];
    float* out       = (float*)d_out;

    void* p;
    cudaGetSymbolAddress(&p, g_hin);  float* hin  = (float*)p;
    cudaGetSymbolAddress(&p, g_hmid); float* hmid = (float*)p;
    cudaGetSymbolAddress(&p, g_xbuf); float* xb   = (float*)p;

    cudaFuncSetAttribute(k_gemm<true>,  cudaFuncAttributeMaxDynamicSharedMemorySize, GEMM_SMEM);
    cudaFuncSetAttribute(k_gemm<false>, cudaFuncAttributeMaxDynamicSharedMemorySize, GEMM_SMEM);

    k_zero_deg<<<(N_NODES + 255) / 256, 256>>>();
    k_hist<<<(N_EDGES + 255) / 256, 256>>>(ei);
    k_scan_part<<<SCAN_BLOCKS, 1024>>>();
    k_scan_top<<<1, 64>>>();
    k_scan_add<<<SCAN_BLOCKS, 1024>>>();
    k_scatter<<<(N_EDGES + 255) / 256, 256>>>(ei);

    const int agg_blocks = (N_NODES * 32 + 255) / 256;
    for (int l = 0; l < N_LAYERS; l++) {
        const float* xin = (l == 0) ? x : xb;
        k_agg<<<agg_blocks, 256>>>(xin, hin);
        k_gemm<true><<<M_TILES, 256, GEMM_SMEM>>>(hin, Ws1 + (size_t)l * DIM * DIM,
                                                  bs1 + (size_t)l * DIM, hmid);
        k_gemm<false><<<M_TILES, 256, GEMM_SMEM>>>(hmid, Ws2 + (size_t)l * DIM * DIM,
                                                   bs2 + (size_t)l * DIM, xb);
    }
    k_pool<<<N_GRAPHS, DIM>>>(xb, bat, out);
}